// round 2
// baseline (speedup 1.0000x reference)
#include <cuda_runtime.h>
#include <math.h>

#define BB 2
#define NN 2048
#define CC 1024
#define HH 16
#define DD 64
#define C3 (3*CC)
#define MM (BB*NN)   /* 4096 rows */

// Scratch (device globals: allocation-free per harness rules)
__device__ float g_q[(size_t)BB*HH*NN*DD];
__device__ float g_k[(size_t)BB*HH*NN*DD];
__device__ float g_v[(size_t)BB*HH*NN*DD];
__device__ float g_ret[(size_t)MM*CC];

// ---------------------------------------------------------------------------
// Kernel 1: qkv = x @ W_qkv + b ; split/scale into g_q (x0.125), g_k, g_v
// laid out [B,H,N,D]. Block tile 64x64, BK=16, 256 thr, 4x4 per thread.
// ---------------------------------------------------------------------------
__global__ void qkv_gemm_kernel(const float* __restrict__ x,
                                const float* __restrict__ W,
                                const float* __restrict__ bias) {
    __shared__ float As[16*65];   // [k][m], pitch 65 (transposed store)
    __shared__ float Bs[16*64];   // [k][n]
    const int bm = blockIdx.y * 64;
    const int bn = blockIdx.x * 64;
    const int tid = threadIdx.x;
    const int tx = tid & 15, ty = tid >> 4;
    float acc[4][4] = {};
    for (int k0 = 0; k0 < CC; k0 += 16) {
        const int kk = tid & 15;
        const int mrow = tid >> 4;
        #pragma unroll
        for (int p = 0; p < 4; p++)
            As[kk*65 + mrow + p*16] = x[(size_t)(bm + mrow + p*16)*CC + k0 + kk];
        const int nc = tid & 63;
        const int kr = tid >> 6;
        #pragma unroll
        for (int p = 0; p < 4; p++)
            Bs[(kr + p*4)*64 + nc] = W[(size_t)(k0 + kr + p*4)*C3 + bn + nc];
        __syncthreads();
        #pragma unroll
        for (int k = 0; k < 16; k++) {
            float a[4], bv[4];
            #pragma unroll
            for (int i = 0; i < 4; i++) a[i] = As[k*65 + ty*4 + i];
            #pragma unroll
            for (int j = 0; j < 4; j++) bv[j] = Bs[k*64 + tx*4 + j];
            #pragma unroll
            for (int i = 0; i < 4; i++)
                #pragma unroll
                for (int j = 0; j < 4; j++)
                    acc[i][j] += a[i]*bv[j];
        }
        __syncthreads();
    }
    // Epilogue: one 64-col tile maps to exactly one (which, head)
    const int which = bn >> 10;            // 0=q,1=k,2=v
    const int h     = (bn >> 6) & (HH-1);
    float* dst = (which == 0) ? g_q : (which == 1) ? g_k : g_v;
    const float qscale = (which == 0) ? 0.125f : 1.0f;  // D^-0.5
    #pragma unroll
    for (int i = 0; i < 4; i++) {
        const int m = bm + ty*4 + i;
        const int b = m >> 11;             // /NN
        const int n = m & (NN-1);
        #pragma unroll
        for (int j = 0; j < 4; j++) {
            const int dd = tx*4 + j;
            const float val = (acc[i][j] + bias[bn + dd]) * qscale;
            dst[(((size_t)b*HH + h)*NN + n)*DD + dd] = val;
        }
    }
}

// ---------------------------------------------------------------------------
// Kernel 2: fused retention. Per (b,h, 64-row q tile):
//   acc = sum_mtiles ( (q k^T) * mask ) v   then  acc += (q @ state_prev)*g^pos
// Exactly 48KB static smem: three 64x64 tiles, zero padding.
// ksh uses XOR swizzle  addr = m*64 + (d ^ (m&31))  for conflict-free use.
// ---------------------------------------------------------------------------
__global__ void retention_attn_kernel(const float* __restrict__ mask,
                                      const float* __restrict__ gamma,
                                      const float* __restrict__ state_prev) {
    __shared__ float qsh[64*64];  // [r][d] natural (reads are broadcast)
    __shared__ float ksh[64*64];  // [m][d] swizzled; reused as ssh[r][m] swz and sp[d][e]
    __shared__ float vsh[64*64];  // [m][e] natural
    const int bh = blockIdx.y;
    const int b = bh >> 4, h = bh & 15;
    const int n0 = blockIdx.x * 64;
    const int tid = threadIdx.x;
    const int tx = tid & 15, ty = tid >> 4;
    const float* qbase = g_q + (size_t)bh*NN*DD;
    const float* kbase = g_k + (size_t)bh*NN*DD;
    const float* vbase = g_v + (size_t)bh*NN*DD;

    // load q tile natural [r][d]
    #pragma unroll
    for (int p = 0; p < 16; p++) {
        const int idx = p*256 + tid;
        const int r = idx >> 6, d = idx & 63;
        qsh[r*64 + d] = qbase[(size_t)(n0 + r)*DD + d];
    }

    // per-thread constants for swizzled reads
    int kcol[4], kbasei[4], rswz[4], rbasei[4];
    #pragma unroll
    for (int j = 0; j < 4; j++) {
        kcol[j]   = (tx*4 + j) & 31;       // swizzle const for k reads
        kbasei[j] = (tx*4 + j) * 64;
    }
    #pragma unroll
    for (int i = 0; i < 4; i++) {
        rswz[i]   = (ty*4 + i) & 31;       // swizzle const for ssh reads
        rbasei[i] = (ty*4 + i) * 64;
    }

    float acc[4][4] = {};
    const float* mbase = mask + ((size_t)h*NN + n0)*NN;

    for (int mt = 0; mt < 32; mt++) {
        const int m0 = mt*64;
        __syncthreads();   // prev-iter readers done (also orders qsh writes on iter 0)
        #pragma unroll
        for (int p = 0; p < 16; p++) {
            const int idx = p*256 + tid;
            const int m = idx >> 6, d = idx & 63;
            ksh[m*64 + (d ^ (m & 31))] = kbase[(size_t)(m0 + m)*DD + d];
            vsh[m*64 + d]              = vbase[(size_t)(m0 + m)*DD + d];
        }
        __syncthreads();

        // s = q k^T  (64x64, 4x4/thread)
        float s[4][4] = {};
        #pragma unroll
        for (int d = 0; d < 64; d++) {
            float a[4], kv[4];
            #pragma unroll
            for (int i = 0; i < 4; i++) a[i] = qsh[rbasei[i] + d];
            #pragma unroll
            for (int j = 0; j < 4; j++) kv[j] = ksh[kbasei[j] + (d ^ kcol[j])];
            #pragma unroll
            for (int i = 0; i < 4; i++)
                #pragma unroll
                for (int j = 0; j < 4; j++)
                    s[i][j] += a[i]*kv[j];
        }
        // s *= mask tile (vectorized row reads)
        #pragma unroll
        for (int i = 0; i < 4; i++) {
            const float4 mv = *(const float4*)(mbase + (size_t)(ty*4 + i)*NN + m0 + tx*4);
            s[i][0] *= mv.x; s[i][1] *= mv.y; s[i][2] *= mv.z; s[i][3] *= mv.w;
        }
        __syncthreads();   // everyone done reading ksh before it becomes ssh
        // write s: ssh[r][m] with swizzle on m
        #pragma unroll
        for (int i = 0; i < 4; i++)
            #pragma unroll
            for (int j = 0; j < 4; j++)
                ksh[rbasei[i] + ((tx*4 + j) ^ rswz[i])] = s[i][j];
        __syncthreads();
        // acc += s @ v
        #pragma unroll
        for (int m = 0; m < 64; m++) {
            float sv[4], vv[4];
            #pragma unroll
            for (int i = 0; i < 4; i++) sv[i] = ksh[rbasei[i] + (m ^ rswz[i])];
            #pragma unroll
            for (int j = 0; j < 4; j++) vv[j] = vsh[m*64 + tx*4 + j];
            #pragma unroll
            for (int i = 0; i < 4; i++)
                #pragma unroll
                for (int j = 0; j < 4; j++)
                    acc[i][j] += sv[i]*vv[j];
        }
    }

    // cross-chunk: acc += (q @ state_prev) * gamma^(pos), pos = global n + 1
    __syncthreads();
    #pragma unroll
    for (int p = 0; p < 16; p++) {
        const int idx = p*256 + tid;
        const int d = idx >> 6, e = idx & 63;
        ksh[d*64 + e] = state_prev[((size_t)bh*DD + d)*DD + e];   // natural, no swizzle
    }
    __syncthreads();
    float cr[4][4] = {};
    #pragma unroll
    for (int d = 0; d < 64; d++) {
        float a[4], sp[4];
        #pragma unroll
        for (int i = 0; i < 4; i++) a[i] = qsh[rbasei[i] + d];
        #pragma unroll
        for (int j = 0; j < 4; j++) sp[j] = ksh[d*64 + tx*4 + j];
        #pragma unroll
        for (int i = 0; i < 4; i++)
            #pragma unroll
            for (int j = 0; j < 4; j++)
                cr[i][j] += a[i]*sp[j];
    }
    const float g  = gamma[h];
    const float lg = logf(g);
    #pragma unroll
    for (int i = 0; i < 4; i++) {
        const int n = n0 + ty*4 + i;
        const float sc = expf(lg * (float)(n + 1));   // gamma^(n+1)
        #pragma unroll
        for (int j = 0; j < 4; j++) acc[i][j] += cr[i][j]*sc;
    }
    // store to g_ret in [B,N,C] layout (C index = h*64 + e)
    #pragma unroll
    for (int i = 0; i < 4; i++) {
        const int n = n0 + ty*4 + i;
        float4 o = make_float4(acc[i][0], acc[i][1], acc[i][2], acc[i][3]);
        *(float4*)(g_ret + ((size_t)b*NN + n)*CC + h*64 + tx*4) = o;
    }
}

// ---------------------------------------------------------------------------
// Kernel 3: state[b,h] = sum_n gamma^(N-1-n) k_n^T v_n + state_prev*gamma^N
// One block per (b,h); decay folded into k at shared-load time.
// ---------------------------------------------------------------------------
__global__ void state_kernel(const float* __restrict__ gamma,
                             const float* __restrict__ state_prev,
                             float* __restrict__ out_state) {
    __shared__ float ksh[64*65];  // [n][d] * decay
    __shared__ float vsh[64*65];  // [n][e]
    const int bh = blockIdx.x;
    const int h = bh & 15;
    const int tid = threadIdx.x;
    const int tx = tid & 15, ty = tid >> 4;
    const float* kbase = g_k + (size_t)bh*NN*DD;
    const float* vbase = g_v + (size_t)bh*NN*DD;
    const float g  = gamma[h];
    const float lg = logf(g);
    float acc[4][4] = {};
    for (int nt = 0; nt < 32; nt++) {
        const int n0 = nt*64;
        __syncthreads();
        #pragma unroll
        for (int p = 0; p < 16; p++) {
            const int idx = p*256 + tid;
            const int r = idx >> 6, d = idx & 63;
            const int n = n0 + r;
            const float decay = expf(lg * (float)(NN - 1 - n));  // gamma^(N-1-n)
            ksh[r*65 + d] = kbase[(size_t)n*DD + d] * decay;
            vsh[r*65 + d] = vbase[(size_t)n*DD + d];
        }
        __syncthreads();
        #pragma unroll
        for (int r = 0; r < 64; r++) {
            float kk[4], vv[4];
            #pragma unroll
            for (int i = 0; i < 4; i++) kk[i] = ksh[r*65 + ty*4 + i];
            #pragma unroll
            for (int j = 0; j < 4; j++) vv[j] = vsh[r*65 + tx*4 + j];
            #pragma unroll
            for (int i = 0; i < 4; i++)
                #pragma unroll
                for (int j = 0; j < 4; j++)
                    acc[i][j] += kk[i]*vv[j];
        }
    }
    const float cd = expf(lg * (float)NN);   // gamma^N
    #pragma unroll
    for (int i = 0; i < 4; i++)
        #pragma unroll
        for (int j = 0; j < 4; j++) {
            const int d = ty*4 + i, e = tx*4 + j;
            const size_t idx = ((size_t)bh*DD + d)*DD + e;
            out_state[idx] = acc[i][j] + state_prev[idx]*cd;
        }
}

// ---------------------------------------------------------------------------
// Kernel 4: out = g_ret @ W_out + b_out  -> d_out[0 : 4096*1024)
// ---------------------------------------------------------------------------
__global__ void out_gemm_kernel(const float* __restrict__ Wout,
                                const float* __restrict__ bout,
                                float* __restrict__ out) {
    __shared__ float As[16*65];
    __shared__ float Bs[16*64];
    const int bm = blockIdx.y * 64;
    const int bn = blockIdx.x * 64;
    const int tid = threadIdx.x;
    const int tx = tid & 15, ty = tid >> 4;
    float acc[4][4] = {};
    for (int k0 = 0; k0 < CC; k0 += 16) {
        const int kk = tid & 15;
        const int mrow = tid >> 4;
        #pragma unroll
        for (int p = 0; p < 4; p++)
            As[kk*65 + mrow + p*16] = g_ret[(size_t)(bm + mrow + p*16)*CC + k0 + kk];
        const int nc = tid & 63;
        const int kr = tid >> 6;
        #pragma unroll
        for (int p = 0; p < 4; p++)
            Bs[(kr + p*4)*64 + nc] = Wout[(size_t)(k0 + kr + p*4)*CC + bn + nc];
        __syncthreads();
        #pragma unroll
        for (int k = 0; k < 16; k++) {
            float a[4], bv[4];
            #pragma unroll
            for (int i = 0; i < 4; i++) a[i] = As[k*65 + ty*4 + i];
            #pragma unroll
            for (int j = 0; j < 4; j++) bv[j] = Bs[k*64 + tx*4 + j];
            #pragma unroll
            for (int i = 0; i < 4; i++)
                #pragma unroll
                for (int j = 0; j < 4; j++)
                    acc[i][j] += a[i]*bv[j];
        }
        __syncthreads();
    }
    #pragma unroll
    for (int i = 0; i < 4; i++) {
        const int m = bm + ty*4 + i;
        #pragma unroll
        for (int j = 0; j < 4; j++) {
            const int col = bn + tx*4 + j;
            out[(size_t)m*CC + col] = acc[i][j] + bout[col];
        }
    }
}

// ---------------------------------------------------------------------------
extern "C" void kernel_launch(void* const* d_in, const int* in_sizes, int n_in,
                              void* d_out, int out_size) {
    const float* x          = (const float*)d_in[0];
    const float* mask       = (const float*)d_in[1];
    const float* gamma      = (const float*)d_in[2];
    const float* state_prev = (const float*)d_in[3];
    const float* W_qkv      = (const float*)d_in[4];
    const float* b_qkv      = (const float*)d_in[5];
    const float* W_out      = (const float*)d_in[6];
    const float* b_out      = (const float*)d_in[7];
    float* out = (float*)d_out;
    float* out_state = out + (size_t)MM*CC;   // state follows out in d_out

    qkv_gemm_kernel<<<dim3(C3/64, MM/64), 256>>>(x, W_qkv, b_qkv);
    retention_attn_kernel<<<dim3(NN/64, BB*HH), 256>>>(mask, gamma, state_prev);
    state_kernel<<<BB*HH, 256>>>(gamma, state_prev, out_state);
    out_gemm_kernel<<<dim3(CC/64, MM/64), 256>>>(W_out, b_out, out);
}

// round 7
// speedup vs baseline: 1.7630x; 1.7630x over previous
#include <cuda_runtime.h>
#include <math.h>
#include <stdint.h>

#define BB 2
#define NN 2048
#define CC 1024
#define HH 16
#define DD 64
#define C3 (3*CC)
#define MM (BB*NN)   /* 4096 rows */

// Scratch (device globals: allocation-free per harness rules)
__device__ float g_q[(size_t)BB*HH*NN*DD];
__device__ float g_k[(size_t)BB*HH*NN*DD];
__device__ float g_v[(size_t)BB*HH*NN*DD];
__device__ float g_ret[(size_t)MM*CC];

__device__ __forceinline__ uint32_t f2tf(float f) {
    uint32_t u; asm("cvt.rna.tf32.f32 %0, %1;" : "=r"(u) : "f"(f)); return u;
}

__device__ __forceinline__ void mma_tf32(float* d,
                                         const uint32_t* a,
                                         const uint32_t* b,
                                         const float* c) {
    asm volatile(
        "mma.sync.aligned.m16n8k8.row.col.f32.tf32.tf32.f32 "
        "{%0,%1,%2,%3}, {%4,%5,%6,%7}, {%8,%9}, {%10,%11,%12,%13};"
        : "=f"(d[0]), "=f"(d[1]), "=f"(d[2]), "=f"(d[3])
        : "r"(a[0]), "r"(a[1]), "r"(a[2]), "r"(a[3]),
          "r"(b[0]), "r"(b[1]),
          "f"(c[0]), "f"(c[1]), "f"(c[2]), "f"(c[3]));
}

// ---------------------------------------------------------------------------
// tf32 GEMM: out[M x N] = A[M x K] * B[K x N] (+bias). Block 128x64, BK=32,
// 8 warps as 4(M) x 2(N), warp tile 32x32 -> mma grid 2(m) x 4(n).
// MODE 0: A = arg (x), epilogue splits/scales into g_q/g_k/g_v.
// MODE 1: A = g_ret (device symbol, resolved IN DEVICE CODE), out + bias.
// ---------------------------------------------------------------------------
template<int MODE>
__global__ void gemm_tf32_kernel(const float* __restrict__ A,
                                 const float* __restrict__ Bm,
                                 const float* __restrict__ bias,
                                 float* __restrict__ out,
                                 int lda, int ldb) {
    __shared__ uint32_t As[32*132];  // [k][m] pitch 132
    __shared__ uint32_t Bs[32*68];   // [k][n] pitch 68
    // Device globals must be resolved in device code, not passed from host
    // (host sees the shadow object; GB300 ATS makes that read 0s).
    const float* __restrict__ Ap = (MODE == 1) ? (const float*)g_ret : A;
    const int bm = blockIdx.y * 128;
    const int bn = blockIdx.x * 64;
    const int tid  = threadIdx.x;
    const int lane = tid & 31;
    const int wid  = tid >> 5;
    const int warpM = wid >> 1;      // 0..3
    const int warpN = wid & 1;       // 0..1
    const int lr = lane >> 2;        // lane/4
    const int lc = lane & 3;         // lane%4

    float acc[2][4][4] = {};

    for (int k0 = 0; k0 < CC; k0 += 32) {
        __syncthreads();
        #pragma unroll
        for (int i = 0; i < 4; i++) {
            const int fidx = i*256 + tid;
            const int row = fidx >> 3;
            const int kq  = (fidx & 7) * 4;
            const float4 v = *(const float4*)(Ap + (size_t)(bm + row)*lda + k0 + kq);
            As[(kq+0)*132 + row] = f2tf(v.x);
            As[(kq+1)*132 + row] = f2tf(v.y);
            As[(kq+2)*132 + row] = f2tf(v.z);
            As[(kq+3)*132 + row] = f2tf(v.w);
        }
        #pragma unroll
        for (int i = 0; i < 2; i++) {
            const int fidx = i*256 + tid;
            const int kr = fidx >> 4;
            const int nq = (fidx & 15) * 4;
            const float4 v = *(const float4*)(Bm + (size_t)(k0 + kr)*ldb + bn + nq);
            Bs[kr*68 + nq + 0] = f2tf(v.x);
            Bs[kr*68 + nq + 1] = f2tf(v.y);
            Bs[kr*68 + nq + 2] = f2tf(v.z);
            Bs[kr*68 + nq + 3] = f2tf(v.w);
        }
        __syncthreads();

        #pragma unroll
        for (int ks = 0; ks < 4; ks++) {
            uint32_t afr[2][4], bfr[4][2];
            #pragma unroll
            for (int mt = 0; mt < 2; mt++) {
                const int row = warpM*32 + mt*16 + lr;
                const int col = ks*8 + lc;
                afr[mt][0] = As[(col  )*132 + row    ];
                afr[mt][1] = As[(col  )*132 + row + 8];
                afr[mt][2] = As[(col+4)*132 + row    ];
                afr[mt][3] = As[(col+4)*132 + row + 8];
            }
            #pragma unroll
            for (int nt = 0; nt < 4; nt++) {
                const int n = warpN*32 + nt*8 + lr;
                bfr[nt][0] = Bs[(ks*8 + lc    )*68 + n];
                bfr[nt][1] = Bs[(ks*8 + lc + 4)*68 + n];
            }
            #pragma unroll
            for (int mt = 0; mt < 2; mt++)
                #pragma unroll
                for (int nt = 0; nt < 4; nt++)
                    mma_tf32(acc[mt][nt], afr[mt], bfr[nt], acc[mt][nt]);
        }
    }

    if (MODE == 0) {
        const int which = bn >> 10;
        const int h     = (bn >> 6) & (HH-1);
        float* dst = (which == 0) ? g_q : (which == 1) ? g_k : g_v;
        const float qscale = (which == 0) ? 0.125f : 1.0f;
        #pragma unroll
        for (int mt = 0; mt < 2; mt++) {
            #pragma unroll
            for (int nt = 0; nt < 4; nt++) {
                const int col = bn + warpN*32 + nt*8 + 2*lc;
                const int dd  = col & 63;
                const float b0 = bias[col], b1 = bias[col+1];
                #pragma unroll
                for (int rh = 0; rh < 2; rh++) {
                    const int m = bm + warpM*32 + mt*16 + lr + rh*8;
                    const int b = m >> 11;
                    const int n = m & (NN-1);
                    float2 o;
                    o.x = (acc[mt][nt][rh*2+0] + b0) * qscale;
                    o.y = (acc[mt][nt][rh*2+1] + b1) * qscale;
                    *(float2*)(dst + (((size_t)b*HH + h)*NN + n)*DD + dd) = o;
                }
            }
        }
    } else {
        #pragma unroll
        for (int mt = 0; mt < 2; mt++) {
            #pragma unroll
            for (int nt = 0; nt < 4; nt++) {
                const int col = bn + warpN*32 + nt*8 + 2*lc;
                const float b0 = bias[col], b1 = bias[col+1];
                #pragma unroll
                for (int rh = 0; rh < 2; rh++) {
                    const int m = bm + warpM*32 + mt*16 + lr + rh*8;
                    float2 o;
                    o.x = acc[mt][nt][rh*2+0] + b0;
                    o.y = acc[mt][nt][rh*2+1] + b1;
                    *(float2*)(out + (size_t)m*CC + col) = o;
                }
            }
        }
    }
}

// ---------------------------------------------------------------------------
// Fused retention (tf32 mma). Per (bh, 32-row q tile):
//   O = sum_mtiles ((q k^T) * mask) v ;  O += (q @ state_prev) * gamma^(n+1)
// 8 warps as 2(M) x 4(N); warp tile 16x16. STATIC smem 43,520 B.
// ---------------------------------------------------------------------------
__global__ void retention_tf32_kernel(const float* __restrict__ mask,
                                      const float* __restrict__ gamma,
                                      const float* __restrict__ state_prev) {
    __shared__ uint32_t qsh[32*68];  // [r][d] pitch 68 (A of mma1/mma3)
    __shared__ uint32_t ksh[64*68];  // [d][m] (B of mma1); reused: P [r][m], sp [d][e]
    __shared__ uint32_t vsh[64*68];  // [m][e] (B of mma2)

    const int bh = blockIdx.y;
    const int b = bh >> 4, h = bh & 15;
    const int n0 = blockIdx.x * 32;
    const int tid  = threadIdx.x;
    const int lane = tid & 31;
    const int wid  = tid >> 5;
    const int warpM = wid >> 2;   // 0..1  (16-row slice)
    const int warpN = wid & 3;    // 0..3  (16-col slice)
    const int lr = lane >> 2, lc = lane & 3;

    const float* qbase = g_q + (size_t)bh*NN*DD;
    const float* kbase = g_k + (size_t)bh*NN*DD;
    const float* vbase = g_v + (size_t)bh*NN*DD;
    // NOTE: no n0 here — rows are indexed globally via rowg below.
    const float* mbase = mask + (size_t)h*NN*NN;

    // load q tile [r][d] (32x64), tf32
    #pragma unroll
    for (int i = 0; i < 2; i++) {
        const int fidx = i*256 + tid;
        const int r = fidx >> 4;
        const int dq = (fidx & 15) * 4;
        const float4 v = *(const float4*)(qbase + (size_t)(n0 + r)*DD + dq);
        qsh[r*68 + dq + 0] = f2tf(v.x);
        qsh[r*68 + dq + 1] = f2tf(v.y);
        qsh[r*68 + dq + 2] = f2tf(v.z);
        qsh[r*68 + dq + 3] = f2tf(v.w);
    }

    const int rl = warpM*16 + lr;   // local q row of c0/c1

    float o[2][4] = {};

    for (int mt = 0; mt < 32; mt++) {
        const int m0 = mt*64;
        __syncthreads();
        // k tile -> ksh[d][m] (transposed), v tile -> vsh[m][e]
        #pragma unroll
        for (int i = 0; i < 4; i++) {
            const int fidx = i*256 + tid;
            const int m = fidx >> 4;
            const int dq = (fidx & 15) * 4;
            const float4 kv = *(const float4*)(kbase + (size_t)(m0 + m)*DD + dq);
            ksh[(dq+0)*68 + m] = f2tf(kv.x);
            ksh[(dq+1)*68 + m] = f2tf(kv.y);
            ksh[(dq+2)*68 + m] = f2tf(kv.z);
            ksh[(dq+3)*68 + m] = f2tf(kv.w);
            const float4 vv = *(const float4*)(vbase + (size_t)(m0 + m)*DD + dq);
            vsh[m*68 + dq + 0] = f2tf(vv.x);
            vsh[m*68 + dq + 1] = f2tf(vv.y);
            vsh[m*68 + dq + 2] = f2tf(vv.z);
            vsh[m*68 + dq + 3] = f2tf(vv.w);
        }
        __syncthreads();

        // S = q k^T  (warp: 16x16)
        float s[2][4] = {};
        #pragma unroll
        for (int ks = 0; ks < 8; ks++) {
            uint32_t afr[4], bfr[2][2];
            const int col = ks*8 + lc;
            afr[0] = qsh[(rl    )*68 + col    ];
            afr[1] = qsh[(rl + 8)*68 + col    ];
            afr[2] = qsh[(rl    )*68 + col + 4];
            afr[3] = qsh[(rl + 8)*68 + col + 4];
            #pragma unroll
            for (int nt = 0; nt < 2; nt++) {
                const int n = warpN*16 + nt*8 + lr;
                bfr[nt][0] = ksh[(col    )*68 + n];
                bfr[nt][1] = ksh[(col + 4)*68 + n];
            }
            #pragma unroll
            for (int nt = 0; nt < 2; nt++)
                mma_tf32(s[nt], afr, bfr[nt], s[nt]);
        }
        // mask multiply (register fragments, direct gmem float2 reads)
        const int rowg = n0 + rl;
        #pragma unroll
        for (int nt = 0; nt < 2; nt++) {
            const int colg = m0 + warpN*16 + nt*8 + 2*lc;
            const float2 m01 = *(const float2*)(mbase + (size_t)rowg*NN + colg);
            const float2 m23 = *(const float2*)(mbase + (size_t)(rowg+8)*NN + colg);
            s[nt][0] *= m01.x; s[nt][1] *= m01.y;
            s[nt][2] *= m23.x; s[nt][3] *= m23.y;
        }
        __syncthreads();   // all warps done reading ksh
        // P -> ksh as [r][m] (32 x 64, pitch 68)
        #pragma unroll
        for (int nt = 0; nt < 2; nt++) {
            const int cl = warpN*16 + nt*8 + 2*lc;
            ksh[(rl    )*68 + cl    ] = f2tf(s[nt][0]);
            ksh[(rl    )*68 + cl + 1] = f2tf(s[nt][1]);
            ksh[(rl + 8)*68 + cl    ] = f2tf(s[nt][2]);
            ksh[(rl + 8)*68 + cl + 1] = f2tf(s[nt][3]);
        }
        __syncthreads();
        // O += P @ V   (k dim = 64 m-positions)
        #pragma unroll
        for (int ks = 0; ks < 8; ks++) {
            uint32_t afr[4], bfr[2][2];
            const int col = ks*8 + lc;
            afr[0] = ksh[(rl    )*68 + col    ];
            afr[1] = ksh[(rl + 8)*68 + col    ];
            afr[2] = ksh[(rl    )*68 + col + 4];
            afr[3] = ksh[(rl + 8)*68 + col + 4];
            #pragma unroll
            for (int nt = 0; nt < 2; nt++) {
                const int n = warpN*16 + nt*8 + lr;
                bfr[nt][0] = vsh[(col    )*68 + n];
                bfr[nt][1] = vsh[(col + 4)*68 + n];
            }
            #pragma unroll
            for (int nt = 0; nt < 2; nt++)
                mma_tf32(o[nt], afr, bfr[nt], o[nt]);
        }
    }

    // cross-chunk: O += (q @ state_prev) * gamma^(n+1)
    __syncthreads();
    #pragma unroll
    for (int i = 0; i < 4; i++) {
        const int fidx = i*256 + tid;
        const int d = fidx >> 4;
        const int eq = (fidx & 15) * 4;
        const float4 v = *(const float4*)(state_prev + ((size_t)bh*DD + d)*DD + eq);
        ksh[d*68 + eq + 0] = f2tf(v.x);
        ksh[d*68 + eq + 1] = f2tf(v.y);
        ksh[d*68 + eq + 2] = f2tf(v.z);
        ksh[d*68 + eq + 3] = f2tf(v.w);
    }
    __syncthreads();
    float cr[2][4] = {};
    #pragma unroll
    for (int ks = 0; ks < 8; ks++) {
        uint32_t afr[4], bfr[2][2];
        const int col = ks*8 + lc;
        afr[0] = qsh[(rl    )*68 + col    ];
        afr[1] = qsh[(rl + 8)*68 + col    ];
        afr[2] = qsh[(rl    )*68 + col + 4];
        afr[3] = qsh[(rl + 8)*68 + col + 4];
        #pragma unroll
        for (int nt = 0; nt < 2; nt++) {
            const int n = warpN*16 + nt*8 + lr;
            bfr[nt][0] = ksh[(col    )*68 + n];
            bfr[nt][1] = ksh[(col + 4)*68 + n];
        }
        #pragma unroll
        for (int nt = 0; nt < 2; nt++)
            mma_tf32(cr[nt], afr, bfr[nt], cr[nt]);
    }
    const float lg = logf(gamma[h]);
    const int rowg = n0 + rl;
    const float sc0 = expf(lg * (float)(rowg + 1));
    const float sc1 = expf(lg * (float)(rowg + 9));
    #pragma unroll
    for (int nt = 0; nt < 2; nt++) {
        o[nt][0] += cr[nt][0]*sc0; o[nt][1] += cr[nt][1]*sc0;
        o[nt][2] += cr[nt][2]*sc1; o[nt][3] += cr[nt][3]*sc1;
    }
    // store to g_ret [B,N,C]
    #pragma unroll
    for (int nt = 0; nt < 2; nt++) {
        const int e = warpN*16 + nt*8 + 2*lc;
        *(float2*)(g_ret + ((size_t)b*NN + rowg    )*CC + h*64 + e) = make_float2(o[nt][0], o[nt][1]);
        *(float2*)(g_ret + ((size_t)b*NN + rowg + 8)*CC + h*64 + e) = make_float2(o[nt][2], o[nt][3]);
    }
}

// ---------------------------------------------------------------------------
// Kernel 3: state[b,h] = sum_n gamma^(N-1-n) k_n^T v_n + state_prev*gamma^N
// ---------------------------------------------------------------------------
__global__ void state_kernel(const float* __restrict__ gamma,
                             const float* __restrict__ state_prev,
                             float* __restrict__ out_state) {
    __shared__ float ksh[64*65];
    __shared__ float vsh[64*65];
    const int bh = blockIdx.x;
    const int h = bh & 15;
    const int tid = threadIdx.x;
    const int tx = tid & 15, ty = tid >> 4;
    const float* kbase = g_k + (size_t)bh*NN*DD;
    const float* vbase = g_v + (size_t)bh*NN*DD;
    const float lg = logf(gamma[h]);
    float acc[4][4] = {};
    for (int nt = 0; nt < 32; nt++) {
        const int n0 = nt*64;
        __syncthreads();
        #pragma unroll
        for (int p = 0; p < 16; p++) {
            const int idx = p*256 + tid;
            const int r = idx >> 6, d = idx & 63;
            const int n = n0 + r;
            const float decay = expf(lg * (float)(NN - 1 - n));
            ksh[r*65 + d] = kbase[(size_t)n*DD + d] * decay;
            vsh[r*65 + d] = vbase[(size_t)n*DD + d];
        }
        __syncthreads();
        #pragma unroll
        for (int r = 0; r < 64; r++) {
            float kk[4], vv[4];
            #pragma unroll
            for (int i = 0; i < 4; i++) kk[i] = ksh[r*65 + ty*4 + i];
            #pragma unroll
            for (int j = 0; j < 4; j++) vv[j] = vsh[r*65 + tx*4 + j];
            #pragma unroll
            for (int i = 0; i < 4; i++)
                #pragma unroll
                for (int j = 0; j < 4; j++)
                    acc[i][j] += kk[i]*vv[j];
        }
    }
    const float cd = expf(lg * (float)NN);
    #pragma unroll
    for (int i = 0; i < 4; i++)
        #pragma unroll
        for (int j = 0; j < 4; j++) {
            const int d = ty*4 + i, e = tx*4 + j;
            const size_t idx = ((size_t)bh*DD + d)*DD + e;
            out_state[idx] = acc[i][j] + state_prev[idx]*cd;
        }
}

// ---------------------------------------------------------------------------
extern "C" void kernel_launch(void* const* d_in, const int* in_sizes, int n_in,
                              void* d_out, int out_size) {
    const float* x          = (const float*)d_in[0];
    const float* mask       = (const float*)d_in[1];
    const float* gamma      = (const float*)d_in[2];
    const float* state_prev = (const float*)d_in[3];
    const float* W_qkv      = (const float*)d_in[4];
    const float* b_qkv      = (const float*)d_in[5];
    const float* W_out      = (const float*)d_in[6];
    const float* b_out      = (const float*)d_in[7];
    float* out = (float*)d_out;
    float* out_state = out + (size_t)MM*CC;

    gemm_tf32_kernel<0><<<dim3(C3/64, MM/128), 256>>>(x, W_qkv, b_qkv, nullptr, CC, C3);
    retention_tf32_kernel<<<dim3(NN/32, BB*HH), 256>>>(mask, gamma, state_prev);
    state_kernel<<<BB*HH, 256>>>(gamma, state_prev, out_state);
    // MODE 1 resolves its A pointer (g_ret) in device code; first arg unused.
    gemm_tf32_kernel<1><<<dim3(CC/64, MM/128), 256>>>(nullptr, W_out, b_out, out, CC, CC);
}

// round 8
// speedup vs baseline: 2.6021x; 1.4760x over previous
#include <cuda_runtime.h>
#include <math.h>
#include <stdint.h>

#define BB 2
#define NN 2048
#define CC 1024
#define HH 16
#define DD 64
#define C3 (3*CC)
#define MM (BB*NN)   /* 4096 rows */

// Scratch (device globals: allocation-free per harness rules)
__device__ float g_q[(size_t)BB*HH*NN*DD];
__device__ float g_k[(size_t)BB*HH*NN*DD];
__device__ float g_v[(size_t)BB*HH*NN*DD];
__device__ float g_ret[(size_t)MM*CC];
__device__ float g_spart[(size_t)BB*HH*32*DD*DD];   // state partials [bh][chunk][d][e]

__device__ __forceinline__ uint32_t f2tf(float f) {
    uint32_t u; asm("cvt.rna.tf32.f32 %0, %1;" : "=r"(u) : "f"(f)); return u;
}

__device__ __forceinline__ void mma_tf32(float* d,
                                         const uint32_t* a,
                                         const uint32_t* b,
                                         const float* c) {
    asm volatile(
        "mma.sync.aligned.m16n8k8.row.col.f32.tf32.tf32.f32 "
        "{%0,%1,%2,%3}, {%4,%5,%6,%7}, {%8,%9}, {%10,%11,%12,%13};"
        : "=f"(d[0]), "=f"(d[1]), "=f"(d[2]), "=f"(d[3])
        : "r"(a[0]), "r"(a[1]), "r"(a[2]), "r"(a[3]),
          "r"(b[0]), "r"(b[1]),
          "f"(c[0]), "f"(c[1]), "f"(c[2]), "f"(c[3]));
}

// ---------------------------------------------------------------------------
// tf32 GEMM: out[M x N] = A[M x K] * B[K x N] (+bias). Block 128x128, BK=32,
// 8 warps as 4(M) x 2(N), warp tile 32x64 -> mma grid 2(m) x 8(n).
// MODE 0: A = arg (x), epilogue splits/scales into g_q/g_k/g_v.
// MODE 1: A = g_ret (device symbol, resolved IN DEVICE CODE), out + bias.
// ---------------------------------------------------------------------------
template<int MODE>
__global__ void __launch_bounds__(256) gemm_tf32_kernel(
        const float* __restrict__ A,
        const float* __restrict__ Bm,
        const float* __restrict__ bias,
        float* __restrict__ out,
        int lda, int ldb) {
    __shared__ uint32_t As[32*132];  // [k][m] pitch 132 (transposed store)
    __shared__ uint32_t Bs[32*136];  // [k][n] pitch 136 (conflict-free frag reads)
    const float* __restrict__ Ap = (MODE == 1) ? (const float*)g_ret : A;
    const int bm = blockIdx.y * 128;
    const int bn = blockIdx.x * 128;
    const int tid  = threadIdx.x;
    const int lane = tid & 31;
    const int wid  = tid >> 5;
    const int warpM = wid >> 1;      // 0..3
    const int warpN = wid & 1;       // 0..1
    const int lr = lane >> 2;
    const int lc = lane & 3;

    float acc[2][8][4] = {};

    for (int k0 = 0; k0 < CC; k0 += 32) {
        __syncthreads();
        // A tile 128x32 -> As[k][m] transposed
        #pragma unroll
        for (int i = 0; i < 4; i++) {
            const int fidx = i*256 + tid;
            const int row = fidx >> 3;
            const int kq  = (fidx & 7) * 4;
            const float4 v = *(const float4*)(Ap + (size_t)(bm + row)*lda + k0 + kq);
            As[(kq+0)*132 + row] = f2tf(v.x);
            As[(kq+1)*132 + row] = f2tf(v.y);
            As[(kq+2)*132 + row] = f2tf(v.z);
            As[(kq+3)*132 + row] = f2tf(v.w);
        }
        // B tile 32x128 -> Bs[k][n], vectorized STS.128
        #pragma unroll
        for (int i = 0; i < 4; i++) {
            const int fidx = i*256 + tid;
            const int kr = fidx >> 5;
            const int nq = (fidx & 31) * 4;
            const float4 v = *(const float4*)(Bm + (size_t)(k0 + kr)*ldb + bn + nq);
            *(uint4*)&Bs[kr*136 + nq] =
                make_uint4(f2tf(v.x), f2tf(v.y), f2tf(v.z), f2tf(v.w));
        }
        __syncthreads();

        #pragma unroll
        for (int ks = 0; ks < 4; ks++) {
            uint32_t afr[2][4], bfr[8][2];
            const int col = ks*8 + lc;
            #pragma unroll
            for (int mt = 0; mt < 2; mt++) {
                const int row = warpM*32 + mt*16 + lr;
                afr[mt][0] = As[(col  )*132 + row    ];
                afr[mt][1] = As[(col  )*132 + row + 8];
                afr[mt][2] = As[(col+4)*132 + row    ];
                afr[mt][3] = As[(col+4)*132 + row + 8];
            }
            #pragma unroll
            for (int nt = 0; nt < 8; nt++) {
                const int n = warpN*64 + nt*8 + lr;
                bfr[nt][0] = Bs[(col    )*136 + n];
                bfr[nt][1] = Bs[(col + 4)*136 + n];
            }
            #pragma unroll
            for (int mt = 0; mt < 2; mt++)
                #pragma unroll
                for (int nt = 0; nt < 8; nt++)
                    mma_tf32(acc[mt][nt], afr[mt], bfr[nt], acc[mt][nt]);
        }
    }

    if (MODE == 0) {
        const int which = bn >> 10;                 // 128 | 1024 so block is in one segment
        float* dst = (which == 0) ? g_q : (which == 1) ? g_k : g_v;
        const float qscale = (which == 0) ? 0.125f : 1.0f;
        #pragma unroll
        for (int mt = 0; mt < 2; mt++) {
            #pragma unroll
            for (int nt = 0; nt < 8; nt++) {
                const int col = bn + warpN*64 + nt*8 + 2*lc;
                const int h   = (col >> 6) & (HH-1);
                const int dd  = col & 63;
                const float b0 = bias[col], b1 = bias[col+1];
                #pragma unroll
                for (int rh = 0; rh < 2; rh++) {
                    const int m = bm + warpM*32 + mt*16 + lr + rh*8;
                    const int b = m >> 11;
                    const int n = m & (NN-1);
                    float2 o;
                    o.x = (acc[mt][nt][rh*2+0] + b0) * qscale;
                    o.y = (acc[mt][nt][rh*2+1] + b1) * qscale;
                    *(float2*)(dst + (((size_t)b*HH + h)*NN + n)*DD + dd) = o;
                }
            }
        }
    } else {
        #pragma unroll
        for (int mt = 0; mt < 2; mt++) {
            #pragma unroll
            for (int nt = 0; nt < 8; nt++) {
                const int col = bn + warpN*64 + nt*8 + 2*lc;
                const float b0 = bias[col], b1 = bias[col+1];
                #pragma unroll
                for (int rh = 0; rh < 2; rh++) {
                    const int m = bm + warpM*32 + mt*16 + lr + rh*8;
                    float2 o;
                    o.x = acc[mt][nt][rh*2+0] + b0;
                    o.y = acc[mt][nt][rh*2+1] + b1;
                    *(float2*)(out + (size_t)m*CC + col) = o;
                }
            }
        }
    }
}

// ---------------------------------------------------------------------------
// Fused retention (tf32 mma). Per (bh, 64-row q tile):
//   O = sum_mtiles ((q k^T) * mask) v ;  O += (q @ state_prev) * gamma^(n+1)
// 8 warps as 4(M) x 2(N); warp tile 16x32. Q fragments live in registers.
// STATIC smem 36,864 B (ksh+vsh, pitch 72 -> conflict-free B-frag reads).
// ---------------------------------------------------------------------------
__global__ void __launch_bounds__(256) retention_tf32_kernel(
        const float* __restrict__ mask,
        const float* __restrict__ gamma,
        const float* __restrict__ state_prev) {
    __shared__ uint32_t ksh[64*72];  // [d][m] (B of QK^T); reused: P [r][m], sp [d][e]
    __shared__ uint32_t vsh[64*72];  // [m][e] (B of PV)

    const int bh = blockIdx.y;
    const int b = bh >> 4, h = bh & 15;
    const int n0 = blockIdx.x * 64;
    const int tid  = threadIdx.x;
    const int lane = tid & 31;
    const int wid  = tid >> 5;
    const int warpM = wid >> 1;   // 0..3  (16-row slice)
    const int warpN = wid & 1;    // 0..1  (32-col slice)
    const int lr = lane >> 2, lc = lane & 3;

    const float* qbase = g_q + (size_t)bh*NN*DD;
    const float* kbase = g_k + (size_t)bh*NN*DD;
    const float* vbase = g_v + (size_t)bh*NN*DD;
    const float* mbase = mask + (size_t)h*NN*NN;   // rows indexed globally below

    const int rl   = warpM*16 + lr;   // local q row (0..63 across warps)
    const int rowg = n0 + rl;         // global q row

    // Q fragments in registers (once per block)
    uint32_t qfr[8][4];
    {
        const float* q0 = qbase + (size_t)rowg*DD;
        const float* q8 = qbase + (size_t)(rowg + 8)*DD;
        #pragma unroll
        for (int ks = 0; ks < 8; ks++) {
            const int col = ks*8 + lc;
            qfr[ks][0] = f2tf(q0[col    ]);
            qfr[ks][1] = f2tf(q8[col    ]);
            qfr[ks][2] = f2tf(q0[col + 4]);
            qfr[ks][3] = f2tf(q8[col + 4]);
        }
    }

    float o[4][4] = {};

    for (int mt = 0; mt < 32; mt++) {
        const int m0 = mt*64;
        __syncthreads();   // prev-iter P/V readers done
        // k tile -> ksh[d][m] (transposed), v tile -> vsh[m][e] (STS.128)
        #pragma unroll
        for (int i = 0; i < 4; i++) {
            const int fidx = i*256 + tid;
            const int m = fidx >> 4;
            const int dq = (fidx & 15) * 4;
            const float4 kv = *(const float4*)(kbase + (size_t)(m0 + m)*DD + dq);
            ksh[(dq+0)*72 + m] = f2tf(kv.x);
            ksh[(dq+1)*72 + m] = f2tf(kv.y);
            ksh[(dq+2)*72 + m] = f2tf(kv.z);
            ksh[(dq+3)*72 + m] = f2tf(kv.w);
            const float4 vv = *(const float4*)(vbase + (size_t)(m0 + m)*DD + dq);
            *(uint4*)&vsh[m*72 + dq] =
                make_uint4(f2tf(vv.x), f2tf(vv.y), f2tf(vv.z), f2tf(vv.w));
        }
        __syncthreads();

        // S = q k^T  (warp: 16x32), A from registers
        float s[4][4] = {};
        #pragma unroll
        for (int ks = 0; ks < 8; ks++) {
            uint32_t bfr[4][2];
            const int col = ks*8 + lc;
            #pragma unroll
            for (int nt = 0; nt < 4; nt++) {
                const int n = warpN*32 + nt*8 + lr;
                bfr[nt][0] = ksh[(col    )*72 + n];
                bfr[nt][1] = ksh[(col + 4)*72 + n];
            }
            #pragma unroll
            for (int nt = 0; nt < 4; nt++)
                mma_tf32(s[nt], qfr[ks], bfr[nt], s[nt]);
        }
        // mask multiply (register fragments, direct gmem float2 reads)
        #pragma unroll
        for (int nt = 0; nt < 4; nt++) {
            const int colg = m0 + warpN*32 + nt*8 + 2*lc;
            const float2 m01 = *(const float2*)(mbase + (size_t)rowg*NN + colg);
            const float2 m23 = *(const float2*)(mbase + (size_t)(rowg+8)*NN + colg);
            s[nt][0] *= m01.x; s[nt][1] *= m01.y;
            s[nt][2] *= m23.x; s[nt][3] *= m23.y;
        }
        __syncthreads();   // all warps done reading ksh
        // P -> ksh as [r][m] (64x64, pitch 72), STS.64 pairs
        #pragma unroll
        for (int nt = 0; nt < 4; nt++) {
            const int cl = warpN*32 + nt*8 + 2*lc;
            *(uint2*)&ksh[(rl    )*72 + cl] = make_uint2(f2tf(s[nt][0]), f2tf(s[nt][1]));
            *(uint2*)&ksh[(rl + 8)*72 + cl] = make_uint2(f2tf(s[nt][2]), f2tf(s[nt][3]));
        }
        __syncthreads();
        // O += P @ V   (k dim = 64 m-positions)
        #pragma unroll
        for (int ks = 0; ks < 8; ks++) {
            uint32_t afr[4], bfr[4][2];
            const int col = ks*8 + lc;
            afr[0] = ksh[(rl    )*72 + col    ];
            afr[1] = ksh[(rl + 8)*72 + col    ];
            afr[2] = ksh[(rl    )*72 + col + 4];
            afr[3] = ksh[(rl + 8)*72 + col + 4];
            #pragma unroll
            for (int nt = 0; nt < 4; nt++) {
                const int n = warpN*32 + nt*8 + lr;
                bfr[nt][0] = vsh[(col    )*72 + n];
                bfr[nt][1] = vsh[(col + 4)*72 + n];
            }
            #pragma unroll
            for (int nt = 0; nt < 4; nt++)
                mma_tf32(o[nt], afr, bfr[nt], o[nt]);
        }
    }

    // cross-chunk: O += (q @ state_prev) * gamma^(n+1)
    __syncthreads();
    #pragma unroll
    for (int i = 0; i < 4; i++) {
        const int fidx = i*256 + tid;
        const int d = fidx >> 4;
        const int eq = (fidx & 15) * 4;
        const float4 v = *(const float4*)(state_prev + ((size_t)bh*DD + d)*DD + eq);
        *(uint4*)&ksh[d*72 + eq] =
            make_uint4(f2tf(v.x), f2tf(v.y), f2tf(v.z), f2tf(v.w));
    }
    __syncthreads();
    float cr[4][4] = {};
    #pragma unroll
    for (int ks = 0; ks < 8; ks++) {
        uint32_t bfr[4][2];
        const int col = ks*8 + lc;
        #pragma unroll
        for (int nt = 0; nt < 4; nt++) {
            const int n = warpN*32 + nt*8 + lr;
            bfr[nt][0] = ksh[(col    )*72 + n];
            bfr[nt][1] = ksh[(col + 4)*72 + n];
        }
        #pragma unroll
        for (int nt = 0; nt < 4; nt++)
            mma_tf32(cr[nt], qfr[ks], bfr[nt], cr[nt]);
    }
    const float lg = logf(gamma[h]);
    const float sc0 = expf(lg * (float)(rowg + 1));
    const float sc1 = expf(lg * (float)(rowg + 9));
    #pragma unroll
    for (int nt = 0; nt < 4; nt++) {
        o[nt][0] += cr[nt][0]*sc0; o[nt][1] += cr[nt][1]*sc0;
        o[nt][2] += cr[nt][2]*sc1; o[nt][3] += cr[nt][3]*sc1;
    }
    // store to g_ret [B,N,C]
    #pragma unroll
    for (int nt = 0; nt < 4; nt++) {
        const int e = warpN*32 + nt*8 + 2*lc;
        *(float2*)(g_ret + ((size_t)b*NN + rowg    )*CC + h*64 + e) = make_float2(o[nt][0], o[nt][1]);
        *(float2*)(g_ret + ((size_t)b*NN + rowg + 8)*CC + h*64 + e) = make_float2(o[nt][2], o[nt][3]);
    }
}

// ---------------------------------------------------------------------------
// Kernel 3a: per-chunk partial state: spart[bh][chunk] = sum_{n in chunk}
//            gamma^(N-1-n) k_n^T v_n   (fp32 SIMT, 64x64 per block)
// ---------------------------------------------------------------------------
__global__ void state_partial_kernel(const float* __restrict__ gamma) {
    __shared__ float ksh[64*65];
    __shared__ float vsh[64*65];
    const int chunk = blockIdx.x;
    const int bh    = blockIdx.y;
    const int h = bh & 15;
    const int tid = threadIdx.x;
    const int tx = tid & 15, ty = tid >> 4;
    const int n0 = chunk * 64;
    const float* kbase = g_k + (size_t)bh*NN*DD;
    const float* vbase = g_v + (size_t)bh*NN*DD;
    const float lg = logf(gamma[h]);
    #pragma unroll
    for (int p = 0; p < 16; p++) {
        const int idx = p*256 + tid;
        const int r = idx >> 6, d = idx & 63;
        const int n = n0 + r;
        const float decay = expf(lg * (float)(NN - 1 - n));
        ksh[r*65 + d] = kbase[(size_t)n*DD + d] * decay;
        vsh[r*65 + d] = vbase[(size_t)n*DD + d];
    }
    __syncthreads();
    float acc[4][4] = {};
    #pragma unroll
    for (int r = 0; r < 64; r++) {
        float kk[4], vv[4];
        #pragma unroll
        for (int i = 0; i < 4; i++) kk[i] = ksh[r*65 + ty*4 + i];
        #pragma unroll
        for (int j = 0; j < 4; j++) vv[j] = vsh[r*65 + tx*4 + j];
        #pragma unroll
        for (int i = 0; i < 4; i++)
            #pragma unroll
            for (int j = 0; j < 4; j++)
                acc[i][j] += kk[i]*vv[j];
    }
    float* dst = g_spart + ((size_t)bh*32 + chunk)*DD*DD;
    #pragma unroll
    for (int i = 0; i < 4; i++)
        #pragma unroll
        for (int j = 0; j < 4; j++)
            dst[(ty*4 + i)*DD + tx*4 + j] = acc[i][j];
}

// ---------------------------------------------------------------------------
// Kernel 3b: reduce partials + state_prev*gamma^N -> out_state
// ---------------------------------------------------------------------------
__global__ void state_reduce_kernel(const float* __restrict__ gamma,
                                    const float* __restrict__ state_prev,
                                    float* __restrict__ out_state) {
    const int bh = blockIdx.x;
    const int h = bh & 15;
    const int tid = threadIdx.x;
    const float cd = expf(logf(gamma[h]) * (float)NN);
    const float* part = g_spart + (size_t)bh*32*DD*DD;
    for (int e = tid; e < DD*DD; e += blockDim.x) {
        float sum = 0.0f;
        #pragma unroll
        for (int c = 0; c < 32; c++) sum += part[(size_t)c*DD*DD + e];
        out_state[(size_t)bh*DD*DD + e] = sum + state_prev[(size_t)bh*DD*DD + e]*cd;
    }
}

// ---------------------------------------------------------------------------
extern "C" void kernel_launch(void* const* d_in, const int* in_sizes, int n_in,
                              void* d_out, int out_size) {
    const float* x          = (const float*)d_in[0];
    const float* mask       = (const float*)d_in[1];
    const float* gamma      = (const float*)d_in[2];
    const float* state_prev = (const float*)d_in[3];
    const float* W_qkv      = (const float*)d_in[4];
    const float* b_qkv      = (const float*)d_in[5];
    const float* W_out      = (const float*)d_in[6];
    const float* b_out      = (const float*)d_in[7];
    float* out = (float*)d_out;
    float* out_state = out + (size_t)MM*CC;

    gemm_tf32_kernel<0><<<dim3(C3/128, MM/128), 256>>>(x, W_qkv, b_qkv, nullptr, CC, C3);
    retention_tf32_kernel<<<dim3(NN/64, BB*HH), 256>>>(mask, gamma, state_prev);
    state_partial_kernel<<<dim3(32, BB*HH), 256>>>(gamma);
    state_reduce_kernel<<<BB*HH, 256>>>(gamma, state_prev, out_state);
    // MODE 1 resolves its A pointer (g_ret) in device code; first arg unused.
    gemm_tf32_kernel<1><<<dim3(CC/128, MM/128), 256>>>(nullptr, W_out, b_out, out, CC, CC);
}

// round 9
// speedup vs baseline: 3.1615x; 1.2150x over previous
#include <cuda_runtime.h>
#include <math.h>
#include <stdint.h>

#define BB 2
#define NN 2048
#define CC 1024
#define HH 16
#define DD 64
#define C3 (3*CC)
#define MM (BB*NN)   /* 4096 rows */

// Scratch (device globals: allocation-free per harness rules)
__device__ float g_q[(size_t)BB*HH*NN*DD];
__device__ float g_k[(size_t)BB*HH*NN*DD];
__device__ float g_v[(size_t)BB*HH*NN*DD];
__device__ float g_ret[(size_t)MM*CC];
__device__ float g_spart[(size_t)BB*HH*32*DD*DD];   // state partials [bh][chunk][d][e]

__device__ __forceinline__ uint32_t f2tf(float f) {
    uint32_t u; asm("cvt.rna.tf32.f32 %0, %1;" : "=r"(u) : "f"(f)); return u;
}

__device__ __forceinline__ void mma_tf32(float* d,
                                         const uint32_t* a,
                                         const uint32_t* b,
                                         const float* c) {
    asm volatile(
        "mma.sync.aligned.m16n8k8.row.col.f32.tf32.tf32.f32 "
        "{%0,%1,%2,%3}, {%4,%5,%6,%7}, {%8,%9}, {%10,%11,%12,%13};"
        : "=f"(d[0]), "=f"(d[1]), "=f"(d[2]), "=f"(d[3])
        : "r"(a[0]), "r"(a[1]), "r"(a[2]), "r"(a[3]),
          "r"(b[0]), "r"(b[1]),
          "f"(c[0]), "f"(c[1]), "f"(c[2]), "f"(c[3]));
}

// ---------------------------------------------------------------------------
// tf32 GEMM: out[M x N] = A[M x K] * B[K x N] (+bias). Block 128x128, BK=32,
// 8 warps as 4(M) x 2(N), warp tile 32x64 -> mma grid 2(m) x 8(n).
// MODE 0: A = arg (x), epilogue splits/scales into g_q/g_k/g_v.
// MODE 1: A = g_ret (device symbol, resolved IN DEVICE CODE), out + bias.
// ---------------------------------------------------------------------------
template<int MODE>
__global__ void __launch_bounds__(256) gemm_tf32_kernel(
        const float* __restrict__ A,
        const float* __restrict__ Bm,
        const float* __restrict__ bias,
        float* __restrict__ out,
        int lda, int ldb) {
    __shared__ uint32_t As[32*132];  // [k][m] pitch 132 (transposed store)
    __shared__ uint32_t Bs[32*136];  // [k][n] pitch 136 (conflict-free frag reads)
    const float* __restrict__ Ap = (MODE == 1) ? (const float*)g_ret : A;
    const int bm = blockIdx.y * 128;
    const int bn = blockIdx.x * 128;
    const int tid  = threadIdx.x;
    const int lane = tid & 31;
    const int wid  = tid >> 5;
    const int warpM = wid >> 1;      // 0..3
    const int warpN = wid & 1;       // 0..1
    const int lr = lane >> 2;
    const int lc = lane & 3;

    float acc[2][8][4] = {};

    for (int k0 = 0; k0 < CC; k0 += 32) {
        __syncthreads();
        // A tile 128x32 -> As[k][m] transposed
        #pragma unroll
        for (int i = 0; i < 4; i++) {
            const int fidx = i*256 + tid;
            const int row = fidx >> 3;
            const int kq  = (fidx & 7) * 4;
            const float4 v = *(const float4*)(Ap + (size_t)(bm + row)*lda + k0 + kq);
            As[(kq+0)*132 + row] = f2tf(v.x);
            As[(kq+1)*132 + row] = f2tf(v.y);
            As[(kq+2)*132 + row] = f2tf(v.z);
            As[(kq+3)*132 + row] = f2tf(v.w);
        }
        // B tile 32x128 -> Bs[k][n], vectorized STS.128
        #pragma unroll
        for (int i = 0; i < 4; i++) {
            const int fidx = i*256 + tid;
            const int kr = fidx >> 5;
            const int nq = (fidx & 31) * 4;
            const float4 v = *(const float4*)(Bm + (size_t)(k0 + kr)*ldb + bn + nq);
            *(uint4*)&Bs[kr*136 + nq] =
                make_uint4(f2tf(v.x), f2tf(v.y), f2tf(v.z), f2tf(v.w));
        }
        __syncthreads();

        #pragma unroll
        for (int ks = 0; ks < 4; ks++) {
            uint32_t afr[2][4], bfr[8][2];
            const int col = ks*8 + lc;
            #pragma unroll
            for (int mt = 0; mt < 2; mt++) {
                const int row = warpM*32 + mt*16 + lr;
                afr[mt][0] = As[(col  )*132 + row    ];
                afr[mt][1] = As[(col  )*132 + row + 8];
                afr[mt][2] = As[(col+4)*132 + row    ];
                afr[mt][3] = As[(col+4)*132 + row + 8];
            }
            #pragma unroll
            for (int nt = 0; nt < 8; nt++) {
                const int n = warpN*64 + nt*8 + lr;
                bfr[nt][0] = Bs[(col    )*136 + n];
                bfr[nt][1] = Bs[(col + 4)*136 + n];
            }
            #pragma unroll
            for (int mt = 0; mt < 2; mt++)
                #pragma unroll
                for (int nt = 0; nt < 8; nt++)
                    mma_tf32(acc[mt][nt], afr[mt], bfr[nt], acc[mt][nt]);
        }
    }

    if (MODE == 0) {
        const int which = bn >> 10;                 // 128 | 1024 so block is in one segment
        float* dst = (which == 0) ? g_q : (which == 1) ? g_k : g_v;
        const float qscale = (which == 0) ? 0.125f : 1.0f;
        #pragma unroll
        for (int mt = 0; mt < 2; mt++) {
            #pragma unroll
            for (int nt = 0; nt < 8; nt++) {
                const int col = bn + warpN*64 + nt*8 + 2*lc;
                const int h   = (col >> 6) & (HH-1);
                const int dd  = col & 63;
                const float b0 = bias[col], b1 = bias[col+1];
                #pragma unroll
                for (int rh = 0; rh < 2; rh++) {
                    const int m = bm + warpM*32 + mt*16 + lr + rh*8;
                    const int b = m >> 11;
                    const int n = m & (NN-1);
                    float2 o;
                    o.x = (acc[mt][nt][rh*2+0] + b0) * qscale;
                    o.y = (acc[mt][nt][rh*2+1] + b1) * qscale;
                    *(float2*)(dst + (((size_t)b*HH + h)*NN + n)*DD + dd) = o;
                }
            }
        }
    } else {
        #pragma unroll
        for (int mt = 0; mt < 2; mt++) {
            #pragma unroll
            for (int nt = 0; nt < 8; nt++) {
                const int col = bn + warpN*64 + nt*8 + 2*lc;
                const float b0 = bias[col], b1 = bias[col+1];
                #pragma unroll
                for (int rh = 0; rh < 2; rh++) {
                    const int m = bm + warpM*32 + mt*16 + lr + rh*8;
                    float2 o;
                    o.x = acc[mt][nt][rh*2+0] + b0;
                    o.y = acc[mt][nt][rh*2+1] + b1;
                    *(float2*)(out + (size_t)m*CC + col) = o;
                }
            }
        }
    }
}

// ---------------------------------------------------------------------------
// Fused retention (tf32 mma). Per (bh, 128-row q tile):
//   O = sum_mtiles ((q k^T) * mask) v ;  O += (q @ state_prev) * gamma^(n+1)
// 8 warps, each owning 16 FULL rows (16 x 64 warp tile). The PV contraction's
// k-dim lies entirely in the warp's own S fragments -> C-frag -> A-frag via
// intra-warp shuffle transpose; NO P smem round-trip; 2 syncs/iter.
// STATIC smem 36,864 B.
// ---------------------------------------------------------------------------
__global__ void __launch_bounds__(256) retention_tf32_kernel(
        const float* __restrict__ mask,
        const float* __restrict__ gamma,
        const float* __restrict__ state_prev) {
    __shared__ uint32_t ksh[64*72];  // [d][m] (B of QK^T); reused: sp [d][e]
    __shared__ uint32_t vsh[64*72];  // [m][e] (B of PV)

    const int bh = blockIdx.y;
    const int b = bh >> 4, h = bh & 15;
    const int n0 = blockIdx.x * 128;
    const int tid  = threadIdx.x;
    const int lane = tid & 31;
    const int wid  = tid >> 5;      // 0..7, each warp = 16 q rows
    const int lr = lane >> 2, lc = lane & 3;

    const float* qbase = g_q + (size_t)bh*NN*DD;
    const float* kbase = g_k + (size_t)bh*NN*DD;
    const float* vbase = g_v + (size_t)bh*NN*DD;
    const float* mbase = mask + (size_t)h*NN*NN;   // rows indexed globally below

    const int rowg = n0 + wid*16 + lr;   // global q row of frag rows (rowg, rowg+8)

    // Q fragments in registers (once per block)
    uint32_t qfr[8][4];
    {
        const float* q0 = qbase + (size_t)rowg*DD;
        const float* q8 = qbase + (size_t)(rowg + 8)*DD;
        #pragma unroll
        for (int ks = 0; ks < 8; ks++) {
            const int col = ks*8 + lc;
            qfr[ks][0] = f2tf(q0[col    ]);
            qfr[ks][1] = f2tf(q8[col    ]);
            qfr[ks][2] = f2tf(q0[col + 4]);
            qfr[ks][3] = f2tf(q8[col + 4]);
        }
    }

    // shuffle-transpose constants: element (r,c) of a 16x64 C-tile lives in
    // lane (r&7)*4 + ((c&7)>>1); A-frag sources:
    const int idxA = lr*4 + (lc >> 1);
    const int idxB = idxA + 2;
    const bool sel = (lc & 1);

    float o[8][4] = {};

    for (int mt = 0; mt < 32; mt++) {
        const int m0 = mt*64;
        __syncthreads();   // prev-iter ksh/vsh readers done
        // k tile -> ksh[d][m] (transposed), v tile -> vsh[m][e] (STS.128)
        #pragma unroll
        for (int i = 0; i < 4; i++) {
            const int fidx = i*256 + tid;
            const int m = fidx >> 4;
            const int dq = (fidx & 15) * 4;
            const float4 kv = *(const float4*)(kbase + (size_t)(m0 + m)*DD + dq);
            ksh[(dq+0)*72 + m] = f2tf(kv.x);
            ksh[(dq+1)*72 + m] = f2tf(kv.y);
            ksh[(dq+2)*72 + m] = f2tf(kv.z);
            ksh[(dq+3)*72 + m] = f2tf(kv.w);
            const float4 vv = *(const float4*)(vbase + (size_t)(m0 + m)*DD + dq);
            *(uint4*)&vsh[m*72 + dq] =
                make_uint4(f2tf(vv.x), f2tf(vv.y), f2tf(vv.z), f2tf(vv.w));
        }
        __syncthreads();

        // S = q k^T  (warp: 16x64), A from registers
        float s[8][4] = {};
        #pragma unroll
        for (int ks = 0; ks < 8; ks++) {
            const int col = ks*8 + lc;
            uint32_t bfr[8][2];
            #pragma unroll
            for (int nt = 0; nt < 8; nt++) {
                const int n = nt*8 + lr;
                bfr[nt][0] = ksh[(col    )*72 + n];
                bfr[nt][1] = ksh[(col + 4)*72 + n];
            }
            #pragma unroll
            for (int nt = 0; nt < 8; nt++)
                mma_tf32(s[nt], qfr[ks], bfr[nt], s[nt]);
        }
        // mask multiply (register fragments, direct gmem float2 reads)
        #pragma unroll
        for (int nt = 0; nt < 8; nt++) {
            const int colg = m0 + nt*8 + 2*lc;
            const float2 m01 = *(const float2*)(mbase + (size_t)rowg*NN + colg);
            const float2 m23 = *(const float2*)(mbase + (size_t)(rowg+8)*NN + colg);
            s[nt][0] *= m01.x; s[nt][1] *= m01.y;
            s[nt][2] *= m23.x; s[nt][3] *= m23.y;
        }
        // O += P @ V : A-frags of P built from own S C-frags by shuffle
        #pragma unroll
        for (int ks = 0; ks < 8; ks++) {
            const float t0A = __shfl_sync(0xffffffffu, s[ks][0], idxA);
            const float t1A = __shfl_sync(0xffffffffu, s[ks][1], idxA);
            const float t2A = __shfl_sync(0xffffffffu, s[ks][2], idxA);
            const float t3A = __shfl_sync(0xffffffffu, s[ks][3], idxA);
            const float t0B = __shfl_sync(0xffffffffu, s[ks][0], idxB);
            const float t1B = __shfl_sync(0xffffffffu, s[ks][1], idxB);
            const float t2B = __shfl_sync(0xffffffffu, s[ks][2], idxB);
            const float t3B = __shfl_sync(0xffffffffu, s[ks][3], idxB);
            uint32_t a[4];
            a[0] = f2tf(sel ? t1A : t0A);
            a[1] = f2tf(sel ? t3A : t2A);
            a[2] = f2tf(sel ? t1B : t0B);
            a[3] = f2tf(sel ? t3B : t2B);
            const int col = ks*8 + lc;
            uint32_t bfr[8][2];
            #pragma unroll
            for (int nt = 0; nt < 8; nt++) {
                const int n = nt*8 + lr;
                bfr[nt][0] = vsh[(col    )*72 + n];
                bfr[nt][1] = vsh[(col + 4)*72 + n];
            }
            #pragma unroll
            for (int nt = 0; nt < 8; nt++)
                mma_tf32(o[nt], a, bfr[nt], o[nt]);
        }
    }

    // cross-chunk: O += (q @ state_prev) * gamma^(n+1)
    __syncthreads();
    #pragma unroll
    for (int i = 0; i < 4; i++) {
        const int fidx = i*256 + tid;
        const int d = fidx >> 4;
        const int eq = (fidx & 15) * 4;
        const float4 v = *(const float4*)(state_prev + ((size_t)bh*DD + d)*DD + eq);
        *(uint4*)&ksh[d*72 + eq] =
            make_uint4(f2tf(v.x), f2tf(v.y), f2tf(v.z), f2tf(v.w));
    }
    __syncthreads();
    float cr[8][4] = {};
    #pragma unroll
    for (int ks = 0; ks < 8; ks++) {
        const int col = ks*8 + lc;
        uint32_t bfr[8][2];
        #pragma unroll
        for (int nt = 0; nt < 8; nt++) {
            const int n = nt*8 + lr;
            bfr[nt][0] = ksh[(col    )*72 + n];
            bfr[nt][1] = ksh[(col + 4)*72 + n];
        }
        #pragma unroll
        for (int nt = 0; nt < 8; nt++)
            mma_tf32(cr[nt], qfr[ks], bfr[nt], cr[nt]);
    }
    const float lg = logf(gamma[h]);
    const float sc0 = expf(lg * (float)(rowg + 1));
    const float sc1 = expf(lg * (float)(rowg + 9));
    #pragma unroll
    for (int nt = 0; nt < 8; nt++) {
        o[nt][0] += cr[nt][0]*sc0; o[nt][1] += cr[nt][1]*sc0;
        o[nt][2] += cr[nt][2]*sc1; o[nt][3] += cr[nt][3]*sc1;
    }
    // store to g_ret [B,N,C]
    #pragma unroll
    for (int nt = 0; nt < 8; nt++) {
        const int e = nt*8 + 2*lc;
        *(float2*)(g_ret + ((size_t)b*NN + rowg    )*CC + h*64 + e) = make_float2(o[nt][0], o[nt][1]);
        *(float2*)(g_ret + ((size_t)b*NN + rowg + 8)*CC + h*64 + e) = make_float2(o[nt][2], o[nt][3]);
    }
}

// ---------------------------------------------------------------------------
// Kernel 3a: per-chunk partial state: spart[bh][chunk] = sum_{n in chunk}
//            gamma^(N-1-n) k_n^T v_n   (fp32 SIMT, 64x64 per block)
// ---------------------------------------------------------------------------
__global__ void state_partial_kernel(const float* __restrict__ gamma) {
    __shared__ float ksh[64*65];
    __shared__ float vsh[64*65];
    const int chunk = blockIdx.x;
    const int bh    = blockIdx.y;
    const int h = bh & 15;
    const int tid = threadIdx.x;
    const int tx = tid & 15, ty = tid >> 4;
    const int n0 = chunk * 64;
    const float* kbase = g_k + (size_t)bh*NN*DD;
    const float* vbase = g_v + (size_t)bh*NN*DD;
    const float lg = logf(gamma[h]);
    #pragma unroll
    for (int p = 0; p < 16; p++) {
        const int idx = p*256 + tid;
        const int r = idx >> 6, d = idx & 63;
        const int n = n0 + r;
        const float decay = expf(lg * (float)(NN - 1 - n));
        ksh[r*65 + d] = kbase[(size_t)n*DD + d] * decay;
        vsh[r*65 + d] = vbase[(size_t)n*DD + d];
    }
    __syncthreads();
    float acc[4][4] = {};
    #pragma unroll
    for (int r = 0; r < 64; r++) {
        float kk[4], vv[4];
        #pragma unroll
        for (int i = 0; i < 4; i++) kk[i] = ksh[r*65 + ty*4 + i];
        #pragma unroll
        for (int j = 0; j < 4; j++) vv[j] = vsh[r*65 + tx*4 + j];
        #pragma unroll
        for (int i = 0; i < 4; i++)
            #pragma unroll
            for (int j = 0; j < 4; j++)
                acc[i][j] += kk[i]*vv[j];
    }
    float* dst = g_spart + ((size_t)bh*32 + chunk)*DD*DD;
    #pragma unroll
    for (int i = 0; i < 4; i++)
        #pragma unroll
        for (int j = 0; j < 4; j++)
            dst[(ty*4 + i)*DD + tx*4 + j] = acc[i][j];
}

// ---------------------------------------------------------------------------
// Kernel 3b: reduce partials + state_prev*gamma^N -> out_state
// ---------------------------------------------------------------------------
__global__ void state_reduce_kernel(const float* __restrict__ gamma,
                                    const float* __restrict__ state_prev,
                                    float* __restrict__ out_state) {
    const int bh = blockIdx.x;
    const int h = bh & 15;
    const int tid = threadIdx.x;
    const float cd = expf(logf(gamma[h]) * (float)NN);
    const float* part = g_spart + (size_t)bh*32*DD*DD;
    for (int e = tid; e < DD*DD; e += blockDim.x) {
        float sum = 0.0f;
        #pragma unroll
        for (int c = 0; c < 32; c++) sum += part[(size_t)c*DD*DD + e];
        out_state[(size_t)bh*DD*DD + e] = sum + state_prev[(size_t)bh*DD*DD + e]*cd;
    }
}

// ---------------------------------------------------------------------------
extern "C" void kernel_launch(void* const* d_in, const int* in_sizes, int n_in,
                              void* d_out, int out_size) {
    const float* x          = (const float*)d_in[0];
    const float* mask       = (const float*)d_in[1];
    const float* gamma      = (const float*)d_in[2];
    const float* state_prev = (const float*)d_in[3];
    const float* W_qkv      = (const float*)d_in[4];
    const float* b_qkv      = (const float*)d_in[5];
    const float* W_out      = (const float*)d_in[6];
    const float* b_out      = (const float*)d_in[7];
    float* out = (float*)d_out;
    float* out_state = out + (size_t)MM*CC;

    gemm_tf32_kernel<0><<<dim3(C3/128, MM/128), 256>>>(x, W_qkv, b_qkv, nullptr, CC, C3);
    retention_tf32_kernel<<<dim3(NN/128, BB*HH), 256>>>(mask, gamma, state_prev);
    state_partial_kernel<<<dim3(32, BB*HH), 256>>>(gamma);
    state_reduce_kernel<<<BB*HH, 256>>>(gamma, state_prev, out_state);
    // MODE 1 resolves its A pointer (g_ret) in device code; first arg unused.
    gemm_tf32_kernel<1><<<dim3(CC/128, MM/128), 256>>>(nullptr, W_out, b_out, out, CC, CC);
}